// round 6
// baseline (speedup 1.0000x reference)
#include <cuda_runtime.h>
#include <math.h>

// ArcFace loss, fused single kernel, warp0-only epilogue (no extra barriers).
//   loss_row = log( sum_c exp(S*clamp(pred)) - exp(S*tgt_cos) + exp(S*tgt_m) ) - S*tgt_m
//   out = mean(loss_row)
// No max-subtraction needed: S*clamp(x) in [-30,30] -> exp in [1e-13,1e13],
// row sum <= 3.2e17, safely inside fp32 range.
//
// exp(S*clamp(x,-1,1)) == ex2( clamp(x*K, -K, K) ) with K = S*log2(e).

#define K_S_LOG2E 43.2808512266689f   // 30 * log2(e)
// cos(0.5), sin(0.5)
#define COS_M     0.8775825618903728f
#define SIN_M     0.479425538604203f
// sin(pi-M)*M = sin(M)*M
#define MM_CONST  (0.479425538604203f * 0.5f)
// cos(pi-M) = -cos(M)
#define THRESH    (-0.8775825618903728f)

#define MAX_ROWS 16384
__device__ float        g_row_loss[MAX_ROWS];
__device__ unsigned int g_done_count;   // zero at load; last block resets to 0

// ex2.approx of clamp(x*K, -K, K): 4 instructions (FMUL-imm, 2x FMNMX, MUFU.EX2)
__device__ __forceinline__ float expS(float x) {
    float y = fminf(K_S_LOG2E, fmaxf(-K_S_LOG2E, x * K_S_LOG2E));
    float r;
    asm("ex2.approx.f32 %0, %1;" : "=f"(r) : "f"(y));
    return r;
}

__device__ __forceinline__ float clamp1(float x) {
    return fminf(1.0f, fmaxf(-1.0f, x));
}

__global__ void __launch_bounds__(256)
arcface_fused_kernel(const float* __restrict__ pred,
                     const void* __restrict__ target,
                     float* __restrict__ out,
                     int C, int n)
{
    const int row  = blockIdx.x;
    const int tid  = threadIdx.x;
    const int lane = tid & 31;
    const int wid  = tid >> 5;

    const float* rowp = pred + (size_t)row * (size_t)C;

    float acc0 = 0.0f, acc1 = 0.0f;

    if (C == 32000) {
        // 8000 float4 per row; 256 threads * 31 iters = 7936, tail 64 vecs.
        // Fixed trip count -> immediate-offset LDG.128s from one base register,
        // no per-iteration IMAD/SETP, front-batched loads (high MLP).
        const float4* p = reinterpret_cast<const float4*>(rowp) + tid;
        #pragma unroll
        for (int j = 0; j < 31; j++) {
            float4 v = p[j * 256];
            acc0 += expS(v.x);
            acc1 += expS(v.y);
            acc0 += expS(v.z);
            acc1 += expS(v.w);
        }
        if (tid < 64) {
            float4 v = p[31 * 256];
            acc0 += expS(v.x);
            acc1 += expS(v.y);
            acc0 += expS(v.z);
            acc1 += expS(v.w);
        }
    } else {
        // Generic fallback.
        const float4* p4 = reinterpret_cast<const float4*>(rowp);
        const int nvec = C >> 2;
        for (int i = tid; i < nvec; i += blockDim.x) {
            float4 v = p4[i];
            acc0 += expS(v.x);
            acc1 += expS(v.y);
            acc0 += expS(v.z);
            acc1 += expS(v.w);
        }
        for (int i = (nvec << 2) + tid; i < C; i += blockDim.x)
            acc0 += expS(rowp[i]);
    }

    float acc = acc0 + acc1;

    // ---- Block reduction (identical to R4).
    __shared__ float warp_sums[8];
    #pragma unroll
    for (int off = 16; off > 0; off >>= 1)
        acc += __shfl_xor_sync(0xFFFFFFFFu, acc, off);
    if (lane == 0) warp_sums[wid] = acc;
    __syncthreads();
    // Warps 1-7 exit here, exactly as in the two-kernel version.

    // ---- Warp-0-only epilogue: dtype detect, margin fixup, done-counter,
    //      and (in the last block only) the global mean. No extra barrier.
    if (wid == 0) {
        const int* w32 = (const int*)target;
        // Interpreted as int32 words, odd indices are either int64 high words
        // (all zero, targets < 32000) or actual int32 targets (OR != 0 w.p. ~1).
        int probe = (2 * lane + 1 < n) ? w32[2 * lane + 1] : 0;
        int any = __reduce_or_sync(0xFFFFFFFFu, probe);

        unsigned int is_last = 0;
        if (lane == 0) {
            float total = 0.0f;
            #pragma unroll
            for (int w = 0; w < 8; w++) total += warp_sums[w];

            long long t = (any == 0) ? ((const long long*)target)[row]
                                     : (long long)w32[row];
            float tc = clamp1(rowp[t]);
            // cos(acos(t)+M) = t*cosM - sqrt(1-t^2)*sinM
            float tm_hard = tc * COS_M - sqrtf(fmaxf(0.0f, 1.0f - tc * tc)) * SIN_M;
            float tm = (tc > THRESH) ? tm_hard : (tc - MM_CONST);
            float sum = total - expS(tc) + expS(tm);
            g_row_loss[row] = logf(sum) - 30.0f * tm;

            // Release-scope atomic: orders the g_row_loss store into L2
            // without an L1 flush.
            unsigned int prev;
            asm volatile("atom.add.release.gpu.global.u32 %0, [%1], %2;"
                         : "=r"(prev)
                         : "l"(&g_done_count), "r"(1u)
                         : "memory");
            is_last = (prev == (unsigned int)(gridDim.x - 1)) ? 1u : 0u;
        }
        is_last = __shfl_sync(0xFFFFFFFFu, is_last, 0);

        if (is_last) {
            // All 8191 other blocks have release-published their row loss.
            asm volatile("fence.acq_rel.gpu;" ::: "memory");
            // n = 8192 -> 2048 float4; 32 lanes x 64 float4 each, fixed order.
            const float4* lp = reinterpret_cast<const float4*>(g_row_loss);
            const int nv4 = n >> 2;
            double d = 0.0;
            #pragma unroll 8
            for (int i = lane; i < nv4; i += 32) {
                float4 v;
                // L2-direct loads: immune to stale L1 lines.
                asm volatile("ld.global.cg.v4.f32 {%0,%1,%2,%3}, [%4];"
                             : "=f"(v.x), "=f"(v.y), "=f"(v.z), "=f"(v.w)
                             : "l"(lp + i));
                d += (double)v.x + (double)v.y + (double)v.z + (double)v.w;
            }
            for (int i = (nv4 << 2) + lane; i < n; i += 32) {
                float s;
                asm volatile("ld.global.cg.f32 %0, [%1];"
                             : "=f"(s) : "l"(g_row_loss + i));
                d += (double)s;
            }
            #pragma unroll
            for (int off = 16; off > 0; off >>= 1)
                d += __shfl_xor_sync(0xFFFFFFFFu, d, off);
            if (lane == 0) {
                out[0] = (float)(d / (double)n);
                g_done_count = 0;                 // reset for next graph replay
            }
        }
    }
}

extern "C" void kernel_launch(void* const* d_in, const int* in_sizes, int n_in,
                              void* d_out, int out_size)
{
    const float* pred   = (const float*)d_in[0];
    const void*  target = d_in[1];
    float*       out    = (float*)d_out;

    const int n = in_sizes[1];              // number of rows (targets)
    const int C = in_sizes[0] / n;          // classes per row

    arcface_fused_kernel<<<n, 256>>>(pred, target, out, C, n);
}

// round 7
// speedup vs baseline: 1.0929x; 1.0929x over previous
#include <cuda_runtime.h>
#include <math.h>

// ArcFace loss, two-kernel streaming formulation + PDL overlap.
//   loss_row = log( sum_c exp(S*clamp(pred)) - exp(S*tgt_cos) + exp(S*tgt_m) ) - S*tgt_m
//   out = mean(loss_row)
// No max-subtraction needed: S*clamp(x) in [-30,30] -> exp in [1e-13,1e13],
// row sum <= 3.2e17, safely inside fp32 range.
//
// exp(S*clamp(x,-1,1)) == ex2( clamp(x*K, -K, K) ) with K = S*log2(e).

#define K_S_LOG2E 43.2808512266689f   // 30 * log2(e)
// cos(0.5), sin(0.5)
#define COS_M     0.8775825618903728f
#define SIN_M     0.479425538604203f
// sin(pi-M)*M = sin(M)*M
#define MM_CONST  (0.479425538604203f * 0.5f)
// cos(pi-M) = -cos(M)
#define THRESH    (-0.8775825618903728f)

#define MAX_ROWS 16384
__device__ float g_row_loss[MAX_ROWS];

// ex2.approx of clamp(x*K, -K, K): 4 instructions (FMUL-imm, 2x FMNMX, MUFU.EX2)
__device__ __forceinline__ float expS(float x) {
    float y = fminf(K_S_LOG2E, fmaxf(-K_S_LOG2E, x * K_S_LOG2E));
    float r;
    asm("ex2.approx.f32 %0, %1;" : "=f"(r) : "f"(y));
    return r;
}

__device__ __forceinline__ float clamp1(float x) {
    return fminf(1.0f, fmaxf(-1.0f, x));
}

__global__ void __launch_bounds__(256)
arcface_row_kernel(const float* __restrict__ pred,
                   const void* __restrict__ target,
                   int C, int n)
{
    const int row  = blockIdx.x;
    const int tid  = threadIdx.x;
    const int lane = tid & 31;
    const int wid  = tid >> 5;

    const float* rowp = pred + (size_t)row * (size_t)C;

    float acc0 = 0.0f, acc1 = 0.0f;

    if (C == 32000) {
        // 8000 float4 per row; 256 threads * 31 iters = 7936, tail 64 vecs.
        // Fixed trip count -> immediate-offset LDG.128s from one base register,
        // no per-iteration IMAD/SETP, front-batched loads (high MLP).
        const float4* p = reinterpret_cast<const float4*>(rowp) + tid;
        #pragma unroll
        for (int j = 0; j < 31; j++) {
            float4 v = p[j * 256];
            acc0 += expS(v.x);
            acc1 += expS(v.y);
            acc0 += expS(v.z);
            acc1 += expS(v.w);
        }
        if (tid < 64) {
            float4 v = p[31 * 256];
            acc0 += expS(v.x);
            acc1 += expS(v.y);
            acc0 += expS(v.z);
            acc1 += expS(v.w);
        }
    } else {
        // Generic fallback.
        const float4* p4 = reinterpret_cast<const float4*>(rowp);
        const int nvec = C >> 2;
        for (int i = tid; i < nvec; i += blockDim.x) {
            float4 v = p4[i];
            acc0 += expS(v.x);
            acc1 += expS(v.y);
            acc0 += expS(v.z);
            acc1 += expS(v.w);
        }
        for (int i = (nvec << 2) + tid; i < C; i += blockDim.x)
            acc0 += expS(rowp[i]);
    }

    float acc = acc0 + acc1;

    // ---- Block reduction.
    __shared__ float warp_sums[8];
    #pragma unroll
    for (int off = 16; off > 0; off >>= 1)
        acc += __shfl_xor_sync(0xFFFFFFFFu, acc, off);
    if (lane == 0) warp_sums[wid] = acc;
    __syncthreads();

    // ---- Target fix-up (warp 0): dtype detect + margin, off the hot path.
    // Interpreted as int32 words, odd indices are either int64 high words
    // (all zero, targets < 32000) or actual int32 targets (OR != 0 w.p. ~1).
    if (wid == 0) {
        const int* w32 = (const int*)target;
        int probe = (2 * lane + 1 < n) ? w32[2 * lane + 1] : 0;
        int any = __reduce_or_sync(0xFFFFFFFFu, probe);
        if (lane == 0) {
            float total = 0.0f;
            #pragma unroll
            for (int w = 0; w < 8; w++) total += warp_sums[w];

            long long t = (any == 0) ? ((const long long*)target)[row]
                                     : (long long)w32[row];
            float tc = clamp1(rowp[t]);
            // cos(acos(t)+M) = t*cosM - sqrt(1-t^2)*sinM
            float tm_hard = tc * COS_M - sqrtf(fmaxf(0.0f, 1.0f - tc * tc)) * SIN_M;
            float tm = (tc > THRESH) ? tm_hard : (tc - MM_CONST);
            // Same expS as in the loop so the target term cancels cleanly.
            float sum = total - expS(tc) + expS(tm);
            g_row_loss[row] = logf(sum) - 30.0f * tm;
        }
    }

    // PDL: this CTA is done; once all CTAs pass this point the dependent
    // grid's griddepcontrol.wait releases with our g_row_loss store visible.
    asm volatile("griddepcontrol.launch_dependents;");
}

__global__ void __launch_bounds__(256)
arcface_reduce_kernel(float* __restrict__ out, int n)
{
    // Launched early via PDL; block until all row-kernel writes are visible.
    asm volatile("griddepcontrol.wait;" ::: "memory");

    const int tid  = threadIdx.x;
    const int lane = tid & 31;
    const int wid  = tid >> 5;

    __shared__ double warp_sums[8];
    const float4* lp = reinterpret_cast<const float4*>(g_row_loss);
    const int nv4 = n >> 2;
    double d = 0.0;
    for (int i = tid; i < nv4; i += 256) {
        float4 v = lp[i];
        d += (double)v.x + (double)v.y + (double)v.z + (double)v.w;
    }
    for (int i = (nv4 << 2) + tid; i < n; i += 256)
        d += (double)g_row_loss[i];

    #pragma unroll
    for (int off = 16; off > 0; off >>= 1)
        d += __shfl_xor_sync(0xFFFFFFFFu, d, off);
    if (lane == 0) warp_sums[wid] = d;
    __syncthreads();
    if (tid == 0) {
        double tot = 0.0;
        #pragma unroll
        for (int w = 0; w < 8; w++) tot += warp_sums[w];
        out[0] = (float)(tot / (double)n);
    }
}

extern "C" void kernel_launch(void* const* d_in, const int* in_sizes, int n_in,
                              void* d_out, int out_size)
{
    const float* pred   = (const float*)d_in[0];
    const void*  target = d_in[1];
    float*       out    = (float*)d_out;

    const int n = in_sizes[1];              // number of rows (targets)
    const int C = in_sizes[0] / n;          // classes per row

    arcface_row_kernel<<<n, 256>>>(pred, target, C, n);

    // Reduce kernel with Programmatic Dependent Launch: its launch latency
    // overlaps the row kernel's tail; griddepcontrol.wait provides ordering.
    cudaLaunchAttribute attrs[1];
    attrs[0].id = cudaLaunchAttributeProgrammaticStreamSerialization;
    attrs[0].val.programmaticStreamSerializationAllowed = 1;

    cudaLaunchConfig_t cfg = {};
    cfg.gridDim  = dim3(1, 1, 1);
    cfg.blockDim = dim3(256, 1, 1);
    cfg.dynamicSmemBytes = 0;
    cfg.stream = 0;
    cfg.attrs = attrs;
    cfg.numAttrs = 1;

    cudaLaunchKernelEx(&cfg, arcface_reduce_kernel, out, n);
}